// round 13
// baseline (speedup 1.0000x reference)
#include <cuda_runtime.h>
#include <cstdint>

#define TSEQ   2048
#define MTOT   4096          // B*T
#define QKROW  1536          // q(1024) | k(256) | v(256)
#define NHEAD  16
#define NKV    4
#define HD     64

// Scratch (no allocation allowed): qkv activations and attention output.
__device__ float g_qkv[(size_t)MTOT * QKROW];
__device__ float g_y[(size_t)MTOT * 1024];

__device__ __forceinline__ float tf32r(float x) {
    uint32_t u;
    asm("cvt.rna.tf32.f32 %0, %1;" : "=r"(u) : "f"(x));
    return __uint_as_float(u);
}
__device__ __forceinline__ uint32_t tf32u(float x) {
    uint32_t u;
    asm("cvt.rna.tf32.f32 %0, %1;" : "=r"(u) : "f"(x));
    return u;
}

__device__ __forceinline__ void mma_tf32(float* d, const uint32_t* a, const uint32_t* b) {
    asm volatile(
        "mma.sync.aligned.m16n8k8.row.col.f32.tf32.tf32.f32 "
        "{%0,%1,%2,%3}, {%4,%5,%6,%7}, {%8,%9}, {%0,%1,%2,%3};\n"
        : "+f"(d[0]), "+f"(d[1]), "+f"(d[2]), "+f"(d[3])
        : "r"(a[0]), "r"(a[1]), "r"(a[2]), "r"(a[3]), "r"(b[0]), "r"(b[1]));
}

__device__ __forceinline__ void cpa16(float* dst, const float* src) {
    uint32_t s = (uint32_t)__cvta_generic_to_shared(dst);
    asm volatile("cp.async.cg.shared.global [%0], [%1], 16;\n" :: "r"(s), "l"(src));
}
__device__ __forceinline__ void cpa_commit() { asm volatile("cp.async.commit_group;\n"); }
__device__ __forceinline__ void cpa_wait0()  { asm volatile("cp.async.wait_group 0;\n" ::: "memory"); }

// ---------------------------------------------------------------------------
// TF32 GEMM (verified R11 version, unchanged). 128x256 block, 64x64 warp
// tiles, cp.async double-buffered; tf32 rounding at fragment load.
// ---------------------------------------------------------------------------
#define ASTRIDE 36
#define ABUF (128 * ASTRIDE)
#define BBUF (256 * ASTRIDE)
#define GBUF (ABUF + BBUF)
#define GSM_BYTES (2 * GBUF * 4)

__device__ __forceinline__
void gemm_body(const float* __restrict__ A, const float* __restrict__ B,
               float* __restrict__ C, int K, int ldc, int coff, int bm,
               float* __restrict__ sm)
{
    const int tid  = threadIdx.x;
    const int wid  = tid >> 5;
    const int lane = tid & 31;
    const int g    = lane >> 2;
    const int qid  = lane & 3;
    const int wm   = (wid >> 2) << 6;   // 0 or 64
    const int wn   = (wid & 3) << 6;    // 0,64,128,192

    float acc[4][8][4];
    #pragma unroll
    for (int mt = 0; mt < 4; mt++)
        #pragma unroll
        for (int nt = 0; nt < 8; nt++)
            #pragma unroll
            for (int r = 0; r < 4; r++) acc[mt][nt][r] = 0.f;

    const int KT = K >> 5;

    auto issue = [&](int kt, float* buf) {
        const float* Ag = A + (size_t)bm * K + (kt << 5);
        #pragma unroll
        for (int it = 0; it < 4; it++) {
            const int ca = tid + (it << 8);
            const int r = ca >> 3, ck = (ca & 7) << 2;
            cpa16(buf + r * ASTRIDE + ck, Ag + (size_t)r * K + ck);
        }
        const float* Bg = B + (kt << 5);
        float* bb = buf + ABUF;
        #pragma unroll
        for (int it = 0; it < 8; it++) {
            const int cb = tid + (it << 8);
            const int r = cb >> 3, ck = (cb & 7) << 2;
            cpa16(bb + r * ASTRIDE + ck, Bg + (size_t)r * K + ck);
        }
        cpa_commit();
    };

    issue(0, sm);
    for (int kt = 0; kt < KT; kt++) {
        cpa_wait0();
        __syncthreads();
        if (kt + 1 < KT) issue(kt + 1, sm + ((kt + 1) & 1) * GBUF);

        const float* As = sm + (kt & 1) * GBUF;
        const float* Bs = As + ABUF;

        #pragma unroll
        for (int kk = 0; kk < 32; kk += 8) {
            uint32_t af[4][4], bf[8][2];
            #pragma unroll
            for (int mt = 0; mt < 4; mt++) {
                const int m0 = wm + (mt << 4) + g;
                af[mt][0] = tf32u(As[(m0    ) * ASTRIDE + kk + qid]);
                af[mt][1] = tf32u(As[(m0 + 8) * ASTRIDE + kk + qid]);
                af[mt][2] = tf32u(As[(m0    ) * ASTRIDE + kk + qid + 4]);
                af[mt][3] = tf32u(As[(m0 + 8) * ASTRIDE + kk + qid + 4]);
            }
            #pragma unroll
            for (int nt = 0; nt < 8; nt++) {
                const int n0 = wn + (nt << 3) + g;
                bf[nt][0] = tf32u(Bs[n0 * ASTRIDE + kk + qid]);
                bf[nt][1] = tf32u(Bs[n0 * ASTRIDE + kk + qid + 4]);
            }
            #pragma unroll
            for (int mt = 0; mt < 4; mt++)
                #pragma unroll
                for (int nt = 0; nt < 8; nt++)
                    mma_tf32(acc[mt][nt], af[mt], bf[nt]);
        }
    }

    #pragma unroll
    for (int mt = 0; mt < 4; mt++) {
        const int r0 = bm + wm + (mt << 4) + g;
        #pragma unroll
        for (int nt = 0; nt < 8; nt++) {
            const int c0 = coff + wn + (nt << 3) + (qid << 1);
            *(float2*)&C[(size_t)r0 * ldc + c0] =
                make_float2(acc[mt][nt][0], acc[mt][nt][1]);
            *(float2*)&C[(size_t)(r0 + 8) * ldc + c0] =
                make_float2(acc[mt][nt][2], acc[mt][nt][3]);
        }
    }
}

// Fused QKV projection: grid (6, 32). 256-col block selects W segment.
__global__ __launch_bounds__(256, 1)
void gemm_qkv(const float* __restrict__ x, const float* __restrict__ Wq,
              const float* __restrict__ Wk, const float* __restrict__ Wv)
{
    extern __shared__ float gsm[];
    const int bx = blockIdx.x;          // 0..5, global col = bx*256
    const float* Bp;
    if (bx < 4)      Bp = Wq + (size_t)(bx << 8) * 1024;
    else if (bx == 4) Bp = Wk;
    else              Bp = Wv;
    gemm_body(x, Bp, g_qkv, 1024, QKROW, bx << 8, blockIdx.y << 7, gsm);
}

// Output projection: out = g_y @ Wo^T, grid (4, 32).
__global__ __launch_bounds__(256, 1)
void gemm_out(const float* __restrict__ Wo, float* __restrict__ out)
{
    extern __shared__ float gsm[];
    gemm_body(g_y, Wo + (size_t)(blockIdx.x << 8) * 1024, out,
              1024, 1024, blockIdx.x << 8, blockIdx.y << 7, gsm);
}

// ---------------------------------------------------------------------------
// Post-process (rotary+rmsnorm on q/k, gated ve add on v). Unchanged.
// ---------------------------------------------------------------------------
__global__ __launch_bounds__(768)
void postproc(const float* __restrict__ x, const float* __restrict__ ve,
              const float* __restrict__ cs, const float* __restrict__ sn,
              const float* __restrict__ Wg)
{
    const int row = blockIdx.x;            // b*T + t
    const int t = row & (TSEQ - 1);
    const int w = threadIdx.x >> 5;
    const int l = threadIdx.x & 31;
    float* base = g_qkv + (size_t)row * QKROW;

    if (w < 20) {
        const int off = (w < 16) ? (w << 6) : (1024 + ((w - 16) << 6));
        float x1 = base[off + l];
        float x2 = base[off + 32 + l];
        float c = cs[t * 32 + l];
        float s = sn[t * 32 + l];
        float a  = x1 * c + x2 * s;
        float bb = x2 * c - x1 * s;
        float ss = a * a + bb * bb;
        #pragma unroll
        for (int d = 16; d >= 1; d >>= 1) ss += __shfl_xor_sync(0xffffffffu, ss, d);
        float r = rsqrtf(ss * (1.0f / 64.0f) + 1.1920929e-7f) * 1.2f;
        base[off + l]      = a  * r;
        base[off + 32 + l] = bb * r;
    } else {
        const int kv = w - 20;
        float dot = (l < 12) ? x[(size_t)row * 1024 + l] * Wg[kv * 12 + l] : 0.f;
        #pragma unroll
        for (int d = 16; d >= 1; d >>= 1) dot += __shfl_xor_sync(0xffffffffu, dot, d);
        float g = 3.0f / (1.0f + __expf(-dot));
        const int off = 1280 + (kv << 6);
        const float* vep = ve + (size_t)row * 256 + (kv << 6);
        base[off + l]      += g * vep[l];
        base[off + 32 + l] += g * vep[32 + l];
    }
}

// ---------------------------------------------------------------------------
// Flash attention, TF32 tensor cores. BM=128 (verified R9/R11 shape, 2 CTA/SM)
// with the GEMM-validated cp.async pipeline: K/V fetched raw fp32 into double
// buffers, tf32 rounding at fragment load (identical rounded values -> rel_err
// bit-identical). Loads for tile t+1 issue right after the top-of-loop barrier,
// overlapping the WHOLE compute of tile t. One __syncthreads per tile.
// smem (dynamic, 106496 B): QP[128][68] | K0[64][68] V0[64][72] | K1 V1.
// ---------------------------------------------------------------------------
#define PADQ 68
#define PADK 68
#define PADV 72
#define OK0 (128 * PADQ)
#define OV0 (OK0 + 64 * PADK)
#define OK1 (OV0 + 64 * PADV)
#define OV1 (OK1 + 64 * PADK)
#define SM_FLOATS (OV1 + 64 * PADV)

__device__ __forceinline__
void kv_issue(const float* __restrict__ kptr, const float* __restrict__ vptr,
              int k0, int tid, float* __restrict__ kd_base,
              float* __restrict__ vd_base)
{
    const int r  = tid >> 2;
    const int c0 = (tid & 3) << 4;
    const float* ks = kptr + (size_t)(k0 + r) * QKROW + c0;
    const float* vs = vptr + (size_t)(k0 + r) * QKROW + c0;
    float* kd = kd_base + r * PADK + c0;   // 68*4=272B row stride, 16B aligned
    float* vd = vd_base + r * PADV + c0;   // 72*4=288B row stride, 16B aligned
    #pragma unroll
    for (int i = 0; i < 16; i += 4) {
        cpa16(kd + i, ks + i);
        cpa16(vd + i, vs + i);
    }
    cpa_commit();
}

__global__ __launch_bounds__(256, 2)
void attn(const int* __restrict__ wlp)
{
    extern __shared__ float sm[];
    float* QP = sm;                 // Q tile, then P (exp scores)

    const int tid  = threadIdx.x;
    const int w    = tid >> 5;
    const int lane = tid & 31;
    const int g    = lane >> 2;
    const int qid  = lane & 3;
    const int qt = blockIdx.x;      // 0..15
    const int h  = blockIdx.y;      // 0..15
    const int b  = blockIdx.z;      // 0..1
    const int window = *wlp;
    const int kv = h >> 2;
    const int q0 = qt << 7;

    const float* rowbase = g_qkv + (size_t)b * TSEQ * QKROW;
    const float* qptr = rowbase + h * 64;
    const float* kptr = rowbase + 1024 + kv * 64;
    const float* vptr = rowbase + 1280 + kv * 64;

    int lo = q0 - window; if (lo < 0) lo = 0;
    const int kt0 = lo >> 6;
    const int ktmax = (q0 + 127) >> 6;

    // issue first K/V tile immediately (overlaps the Q load below)
    kv_issue(kptr, vptr, kt0 << 6, tid, sm + OK0, sm + OV0);

    {   // load Q tile (warp w loads exactly its own rows 16w..16w+15)
        const int r = tid >> 1;
        const int c0 = (tid & 1) << 5;
        const float* src = qptr + (size_t)(q0 + r) * QKROW + c0;
        float* dst = QP + r * PADQ + c0;
        #pragma unroll
        for (int i = 0; i < 32; i += 4) {
            float4 v4 = *(const float4*)(src + i);
            dst[i+0] = tf32r(v4.x); dst[i+1] = tf32r(v4.y);
            dst[i+2] = tf32r(v4.z); dst[i+3] = tf32r(v4.w);
        }
    }
    __syncwarp();

    const int mrow = (w << 4) + g;
    const int qlo = q0 + mrow;
    const int qhi = qlo + 8;

    // Hoist Q fragments to registers (loop-invariant); QP then freed for P.
    uint32_t qf[8][4];
    #pragma unroll
    for (int k8 = 0; k8 < 8; k8++) {
        qf[k8][0] = __float_as_uint(QP[(mrow    ) * PADQ + (k8 << 3) + qid]);
        qf[k8][1] = __float_as_uint(QP[(mrow + 8) * PADQ + (k8 << 3) + qid]);
        qf[k8][2] = __float_as_uint(QP[(mrow    ) * PADQ + (k8 << 3) + qid + 4]);
        qf[k8][3] = __float_as_uint(QP[(mrow + 8) * PADQ + (k8 << 3) + qid + 4]);
    }
    __syncwarp();

    float o[8][4];
    #pragma unroll
    for (int nt = 0; nt < 8; nt++)
        #pragma unroll
        for (int r = 0; r < 4; r++) o[nt][r] = 0.f;
    float m_lo = -1e30f, m_hi = -1e30f, l_lo = 0.f, l_hi = 0.f;

    int p = 0;
    for (int kt = kt0; kt <= ktmax; kt++) {
        const int k0 = kt << 6;
        cpa_wait0();
        __syncthreads();    // tile kt resident; buffer !p fully consumed by all warps
        if (kt < ktmax)     // issue next tile now -> overlaps ALL compute below
            kv_issue(kptr, vptr, (kt + 1) << 6, tid,
                     sm + (p ? OK0 : OK1), sm + (p ? OV0 : OV1));

        const float* Kc = sm + (p ? OK1 : OK0);
        const float* Vc = sm + (p ? OV1 : OV0);

        // ---- S = Q K^T (16 x 64 per warp); tf32 rounding at frag load ----
        float s[8][4];
        #pragma unroll
        for (int nt = 0; nt < 8; nt++)
            #pragma unroll
            for (int r = 0; r < 4; r++) s[nt][r] = 0.f;
        #pragma unroll
        for (int k8 = 0; k8 < 8; k8++) {
            const int kk = k8 << 3;
            #pragma unroll
            for (int nt = 0; nt < 8; nt++) {
                uint32_t bfr[2];
                bfr[0] = tf32u(Kc[((nt << 3) + g) * PADK + kk + qid]);
                bfr[1] = tf32u(Kc[((nt << 3) + g) * PADK + kk + qid + 4]);
                mma_tf32(s[nt], qf[k8], bfr);
            }
        }

        // ---- mask + online softmax (warp-local rows) ----
        const bool interior = (k0 + 63 <= q0) && (q0 + 127 - k0 <= window);
        float rx_lo = -1e30f, rx_hi = -1e30f;
        if (interior) {
            #pragma unroll
            for (int nt = 0; nt < 8; nt++) {
                #pragma unroll
                for (int c = 0; c < 2; c++) {
                    s[nt][c]     *= 0.125f;
                    s[nt][2 + c] *= 0.125f;
                    rx_lo = fmaxf(rx_lo, s[nt][c]);
                    rx_hi = fmaxf(rx_hi, s[nt][2 + c]);
                }
            }
        } else {
            #pragma unroll
            for (int nt = 0; nt < 8; nt++) {
                #pragma unroll
                for (int c = 0; c < 2; c++) {
                    const int kj = k0 + (nt << 3) + (qid << 1) + c;
                    const bool ok_lo = (kj <= qlo) && (qlo - kj <= window);
                    const bool ok_hi = (kj <= qhi) && (qhi - kj <= window);
                    s[nt][c]     = ok_lo ? s[nt][c]     * 0.125f : -1e30f;
                    s[nt][2 + c] = ok_hi ? s[nt][2 + c] * 0.125f : -1e30f;
                    rx_lo = fmaxf(rx_lo, s[nt][c]);
                    rx_hi = fmaxf(rx_hi, s[nt][2 + c]);
                }
            }
        }
        rx_lo = fmaxf(rx_lo, __shfl_xor_sync(0xffffffffu, rx_lo, 1));
        rx_lo = fmaxf(rx_lo, __shfl_xor_sync(0xffffffffu, rx_lo, 2));
        rx_hi = fmaxf(rx_hi, __shfl_xor_sync(0xffffffffu, rx_hi, 1));
        rx_hi = fmaxf(rx_hi, __shfl_xor_sync(0xffffffffu, rx_hi, 2));

        const float mn_lo = fmaxf(m_lo, rx_lo);
        const float mn_hi = fmaxf(m_hi, rx_hi);
        const float cr_lo = __expf(m_lo - mn_lo);
        const float cr_hi = __expf(m_hi - mn_hi);
        float rs_lo = 0.f, rs_hi = 0.f;
        #pragma unroll
        for (int nt = 0; nt < 8; nt++) {
            float e0 = __expf(s[nt][0] - mn_lo);
            float e1 = __expf(s[nt][1] - mn_lo);
            float e2 = __expf(s[nt][2] - mn_hi);
            float e3 = __expf(s[nt][3] - mn_hi);
            rs_lo += e0 + e1;
            rs_hi += e2 + e3;
            const int pc = (nt << 3) + (qid << 1);
            *(float2*)&QP[(mrow    ) * PADQ + pc] = make_float2(tf32r(e0), tf32r(e1));
            *(float2*)&QP[(mrow + 8) * PADQ + pc] = make_float2(tf32r(e2), tf32r(e3));
        }
        rs_lo += __shfl_xor_sync(0xffffffffu, rs_lo, 1);
        rs_lo += __shfl_xor_sync(0xffffffffu, rs_lo, 2);
        rs_hi += __shfl_xor_sync(0xffffffffu, rs_hi, 1);
        rs_hi += __shfl_xor_sync(0xffffffffu, rs_hi, 2);
        m_lo = mn_lo; m_hi = mn_hi;
        l_lo = l_lo * cr_lo + rs_lo;
        l_hi = l_hi * cr_hi + rs_hi;
        #pragma unroll
        for (int nt = 0; nt < 8; nt++) {
            o[nt][0] *= cr_lo; o[nt][1] *= cr_lo;
            o[nt][2] *= cr_hi; o[nt][3] *= cr_hi;
        }
        __syncwarp();   // P rows visible across own warp's lanes

        // ---- O += P V (16 x 64 per warp) ----
        #pragma unroll
        for (int k8 = 0; k8 < 8; k8++) {
            const int kk = k8 << 3;
            uint32_t a[4];
            a[0] = __float_as_uint(QP[(mrow    ) * PADQ + kk + qid]);
            a[1] = __float_as_uint(QP[(mrow + 8) * PADQ + kk + qid]);
            a[2] = __float_as_uint(QP[(mrow    ) * PADQ + kk + qid + 4]);
            a[3] = __float_as_uint(QP[(mrow + 8) * PADQ + kk + qid + 4]);
            #pragma unroll
            for (int nt = 0; nt < 8; nt++) {
                uint32_t bfr[2];
                bfr[0] = tf32u(Vc[(kk + qid    ) * PADV + (nt << 3) + g]);
                bfr[1] = tf32u(Vc[(kk + qid + 4) * PADV + (nt << 3) + g]);
                mma_tf32(o[nt], a, bfr);
            }
        }
        __syncwarp();   // PV reads done before next tile's P overwrite
        p ^= 1;
    }

    const float inv_lo = 1.0f / l_lo;
    const float inv_hi = 1.0f / l_hi;
    float* ylo = g_y + (size_t)(b * TSEQ + qlo) * 1024 + h * 64;
    float* yhi = g_y + (size_t)(b * TSEQ + qhi) * 1024 + h * 64;
    #pragma unroll
    for (int nt = 0; nt < 8; nt++) {
        const int c = (nt << 3) + (qid << 1);
        *(float2*)(ylo + c) = make_float2(o[nt][0] * inv_lo, o[nt][1] * inv_lo);
        *(float2*)(yhi + c) = make_float2(o[nt][2] * inv_hi, o[nt][3] * inv_hi);
    }
}

// ---------------------------------------------------------------------------
extern "C" void kernel_launch(void* const* d_in, const int* in_sizes, int n_in,
                              void* d_out, int out_size)
{
    const float* x  = (const float*)d_in[0];
    const float* ve = (const float*)d_in[1];
    const float* cs = (const float*)d_in[2];
    const float* sn = (const float*)d_in[3];
    const float* Wq = (const float*)d_in[4];
    const float* Wk = (const float*)d_in[5];
    const float* Wv = (const float*)d_in[6];
    const float* Wo = (const float*)d_in[7];
    const float* Wg = (const float*)d_in[8];
    const int*   wl = (const int*)d_in[9];
    float* out = (float*)d_out;

    // Idempotent host-side calls; safe under graph capture, no static guards.
    cudaFuncSetAttribute(attn, cudaFuncAttributeMaxDynamicSharedMemorySize,
                         SM_FLOATS * sizeof(float));
    cudaFuncSetAttribute(gemm_qkv, cudaFuncAttributeMaxDynamicSharedMemorySize,
                         GSM_BYTES);
    cudaFuncSetAttribute(gemm_out, cudaFuncAttributeMaxDynamicSharedMemorySize,
                         GSM_BYTES);

    // Fused QKV projection -> g_qkv rows [q(1024) | k(256) | v(256)]
    gemm_qkv<<<dim3(6, 32), 256, GSM_BYTES>>>(x, Wq, Wk, Wv);

    // gate*ve add, rotary + rmsnorm * QK_SCALE
    postproc<<<MTOT, 768>>>(x, ve, cs, sn, Wg);

    // sliding-window flash attention (TF32 tensor cores) -> g_y
    attn<<<dim3(16, NHEAD, 2), 256, SM_FLOATS * sizeof(float)>>>(wl);

    // output projection: out = g_y @ Wo^T
    gemm_out<<<dim3(4, 32), 256, GSM_BYTES>>>(Wo, out);
}

// round 14
// speedup vs baseline: 1.2919x; 1.2919x over previous
#include <cuda_runtime.h>
#include <cuda_fp16.h>
#include <cstdint>

#define TSEQ   2048
#define MTOT   4096          // B*T
#define QKROW  1536          // q(1024) | k(256) | v(256)
#define NHEAD  16
#define NKV    4
#define HD     64

// Scratch (no allocation allowed).
__device__ float  g_qkv[(size_t)MTOT * QKROW];
__device__ __half g_x_h[(size_t)MTOT * 1024];
__device__ __half g_wq_h[1024 * 1024];
__device__ __half g_wk_h[256 * 1024];
__device__ __half g_wv_h[256 * 1024];
__device__ __half g_wo_h[1024 * 1024];
__device__ __half g_y_h[(size_t)MTOT * 1024];

__device__ __forceinline__ float tf32r(float x) {
    uint32_t u;
    asm("cvt.rna.tf32.f32 %0, %1;" : "=r"(u) : "f"(x));
    return __uint_as_float(u);
}

__device__ __forceinline__ void mma_tf32(float* d, const uint32_t* a, const uint32_t* b) {
    asm volatile(
        "mma.sync.aligned.m16n8k8.row.col.f32.tf32.tf32.f32 "
        "{%0,%1,%2,%3}, {%4,%5,%6,%7}, {%8,%9}, {%0,%1,%2,%3};\n"
        : "+f"(d[0]), "+f"(d[1]), "+f"(d[2]), "+f"(d[3])
        : "r"(a[0]), "r"(a[1]), "r"(a[2]), "r"(a[3]), "r"(b[0]), "r"(b[1]));
}

__device__ __forceinline__ void mma_f16(float* d, const uint32_t* a, const uint32_t* b) {
    asm volatile(
        "mma.sync.aligned.m16n8k16.row.col.f32.f16.f16.f32 "
        "{%0,%1,%2,%3}, {%4,%5,%6,%7}, {%8,%9}, {%0,%1,%2,%3};\n"
        : "+f"(d[0]), "+f"(d[1]), "+f"(d[2]), "+f"(d[3])
        : "r"(a[0]), "r"(a[1]), "r"(a[2]), "r"(a[3]), "r"(b[0]), "r"(b[1]));
}

__device__ __forceinline__ void cpa16h(__half* dst, const __half* src) {
    uint32_t s = (uint32_t)__cvta_generic_to_shared(dst);
    asm volatile("cp.async.cg.shared.global [%0], [%1], 16;\n" :: "r"(s), "l"(src));
}
__device__ __forceinline__ void cpa_commit() { asm volatile("cp.async.commit_group;\n"); }
__device__ __forceinline__ void cpa_wait0()  { asm volatile("cp.async.wait_group 0;\n" ::: "memory"); }

// ---------------------------------------------------------------------------
// Prep: convert x + weights to fp16 (one pass; HBM-bound ~10us).
// ---------------------------------------------------------------------------
#define NX4 1048576   // x        4096*1024/4
#define NQ4 393216    // Wq       1024*1024... (1536-512)? Wq is 1024x1024 -> 262144
// segment quad counts (float4 units)
#define SX  1048576                   // x: 4096*1024/4
#define SQ  (SX + 262144)             // Wq: 1024*1024/4
#define SK  (SQ + 65536)              // Wk: 256*1024/4
#define SV  (SK + 65536)              // Wv: 256*1024/4
#define SO  (SV + 262144)             // Wo: 1024*1024/4

__global__ __launch_bounds__(256)
void to_half(const float* __restrict__ x, const float* __restrict__ wq,
             const float* __restrict__ wk, const float* __restrict__ wv,
             const float* __restrict__ wo)
{
    const int i = blockIdx.x * 256 + threadIdx.x;
    const float* src; __half* dst; int j;
    if      (i < SX) { src = x;  dst = g_x_h;  j = i; }
    else if (i < SQ) { src = wq; dst = g_wq_h; j = i - SX; }
    else if (i < SK) { src = wk; dst = g_wk_h; j = i - SQ; }
    else if (i < SV) { src = wv; dst = g_wv_h; j = i - SK; }
    else if (i < SO) { src = wo; dst = g_wo_h; j = i - SV; }
    else return;
    float4 v = ((const float4*)src)[j];
    __half2* d2 = (__half2*)dst;
    d2[j * 2]     = __floats2half2_rn(v.x, v.y);
    d2[j * 2 + 1] = __floats2half2_rn(v.z, v.w);
}

// ---------------------------------------------------------------------------
// FP16 GEMM: C[m][coff+n] = sum_k A[m][k]*B[n][k], fp32 accum/output.
// 128x256 block, BK=32, 8 warps (2m x 4n), warp tile 64x64 (4mt x 8nt
// m16n8k16). cp.async double-buffered (verified R11 skeleton, fp16-typed).
// smem row stride 40 halves (20 words): frag loads conflict-free
// (bank = 20g+qid distinct mod 32), cp.async stores 4-phase optimal.
// ---------------------------------------------------------------------------
#define HSTRIDE 40
#define HABUF (128 * HSTRIDE)
#define HBBUF (256 * HSTRIDE)
#define HBUF  (HABUF + HBBUF)
#define HSM_BYTES (2 * HBUF * 2)

__device__ __forceinline__
void gemm_body_h(const __half* __restrict__ A, const __half* __restrict__ B,
                 float* __restrict__ C, int K, int ldc, int coff, int bm,
                 __half* __restrict__ sm)
{
    const int tid  = threadIdx.x;
    const int wid  = tid >> 5;
    const int lane = tid & 31;
    const int g    = lane >> 2;
    const int qid  = lane & 3;
    const int wm   = (wid >> 2) << 6;   // 0 or 64
    const int wn   = (wid & 3) << 6;    // 0,64,128,192

    float acc[4][8][4];
    #pragma unroll
    for (int mt = 0; mt < 4; mt++)
        #pragma unroll
        for (int nt = 0; nt < 8; nt++)
            #pragma unroll
            for (int r = 0; r < 4; r++) acc[mt][nt][r] = 0.f;

    const int KT = K >> 5;

    auto issue = [&](int kt, __half* buf) {
        const __half* Ag = A + (size_t)bm * K + (kt << 5);
        #pragma unroll
        for (int it = 0; it < 2; it++) {
            const int s = tid + (it << 8);
            const int r = s >> 2, c8 = (s & 3) << 3;
            cpa16h(buf + r * HSTRIDE + c8, Ag + (size_t)r * K + c8);
        }
        const __half* Bg = B + (kt << 5);
        __half* bb = buf + HABUF;
        #pragma unroll
        for (int it = 0; it < 4; it++) {
            const int s = tid + (it << 8);
            const int r = s >> 2, c8 = (s & 3) << 3;
            cpa16h(bb + r * HSTRIDE + c8, Bg + (size_t)r * K + c8);
        }
        cpa_commit();
    };

    issue(0, sm);
    for (int kt = 0; kt < KT; kt++) {
        cpa_wait0();
        __syncthreads();
        if (kt + 1 < KT) issue(kt + 1, sm + ((kt + 1) & 1) * HBUF);

        const __half* As = sm + (kt & 1) * HBUF;
        const __half* Bs = As + HABUF;

        #pragma unroll
        for (int ks = 0; ks < 2; ks++) {      // two m16n8k16 steps per BK=32
            const int kw = ks << 3;           // word offset within row
            uint32_t af[4][4], bf[8][2];
            #pragma unroll
            for (int mt = 0; mt < 4; mt++) {
                const int m0 = wm + (mt << 4) + g;
                const uint32_t* Ar  = (const uint32_t*)(As + m0 * HSTRIDE);
                const uint32_t* Ar8 = (const uint32_t*)(As + (m0 + 8) * HSTRIDE);
                af[mt][0] = Ar [kw + qid];
                af[mt][1] = Ar8[kw + qid];
                af[mt][2] = Ar [kw + qid + 4];
                af[mt][3] = Ar8[kw + qid + 4];
            }
            #pragma unroll
            for (int nt = 0; nt < 8; nt++) {
                const int n0 = wn + (nt << 3) + g;
                const uint32_t* Br = (const uint32_t*)(Bs + n0 * HSTRIDE);
                bf[nt][0] = Br[kw + qid];
                bf[nt][1] = Br[kw + qid + 4];
            }
            #pragma unroll
            for (int mt = 0; mt < 4; mt++)
                #pragma unroll
                for (int nt = 0; nt < 8; nt++)
                    mma_f16(acc[mt][nt], af[mt], bf[nt]);
        }
    }

    #pragma unroll
    for (int mt = 0; mt < 4; mt++) {
        const int r0 = bm + wm + (mt << 4) + g;
        #pragma unroll
        for (int nt = 0; nt < 8; nt++) {
            const int c0 = coff + wn + (nt << 3) + (qid << 1);
            *(float2*)&C[(size_t)r0 * ldc + c0] =
                make_float2(acc[mt][nt][0], acc[mt][nt][1]);
            *(float2*)&C[(size_t)(r0 + 8) * ldc + c0] =
                make_float2(acc[mt][nt][2], acc[mt][nt][3]);
        }
    }
}

// Fused QKV projection: grid (6, 32). 256-col block selects W segment.
__global__ __launch_bounds__(256, 1)
void gemm_qkv(int dummy)
{
    extern __shared__ __half hsm[];
    const int bx = blockIdx.x;          // 0..5, global col = bx*256
    const __half* Bp;
    if (bx < 4)       Bp = g_wq_h + (size_t)(bx << 8) * 1024;
    else if (bx == 4) Bp = g_wk_h;
    else              Bp = g_wv_h;
    gemm_body_h(g_x_h, Bp, g_qkv, 1024, QKROW, bx << 8, blockIdx.y << 7, hsm);
}

// Output projection: out = g_y @ Wo^T, grid (4, 32).
__global__ __launch_bounds__(256, 1)
void gemm_out(float* __restrict__ out)
{
    extern __shared__ __half hsm[];
    gemm_body_h(g_y_h, g_wo_h + (size_t)(blockIdx.x << 8) * 1024, out,
                1024, 1024, blockIdx.x << 8, blockIdx.y << 7, hsm);
}

// ---------------------------------------------------------------------------
// Post-process (rotary+rmsnorm on q/k, gated ve add on v). Unchanged.
// ---------------------------------------------------------------------------
__global__ __launch_bounds__(768)
void postproc(const float* __restrict__ x, const float* __restrict__ ve,
              const float* __restrict__ cs, const float* __restrict__ sn,
              const float* __restrict__ Wg)
{
    const int row = blockIdx.x;            // b*T + t
    const int t = row & (TSEQ - 1);
    const int w = threadIdx.x >> 5;
    const int l = threadIdx.x & 31;
    float* base = g_qkv + (size_t)row * QKROW;

    if (w < 20) {
        const int off = (w < 16) ? (w << 6) : (1024 + ((w - 16) << 6));
        float x1 = base[off + l];
        float x2 = base[off + 32 + l];
        float c = cs[t * 32 + l];
        float s = sn[t * 32 + l];
        float a  = x1 * c + x2 * s;
        float bb = x2 * c - x1 * s;
        float ss = a * a + bb * bb;
        #pragma unroll
        for (int d = 16; d >= 1; d >>= 1) ss += __shfl_xor_sync(0xffffffffu, ss, d);
        float r = rsqrtf(ss * (1.0f / 64.0f) + 1.1920929e-7f) * 1.2f;
        base[off + l]      = a  * r;
        base[off + 32 + l] = bb * r;
    } else {
        const int kv = w - 20;
        float dot = (l < 12) ? x[(size_t)row * 1024 + l] * Wg[kv * 12 + l] : 0.f;
        #pragma unroll
        for (int d = 16; d >= 1; d >>= 1) dot += __shfl_xor_sync(0xffffffffu, dot, d);
        float g = 3.0f / (1.0f + __expf(-dot));
        const int off = 1280 + (kv << 6);
        const float* vep = ve + (size_t)row * 256 + (kv << 6);
        base[off + l]      += g * vep[l];
        base[off + 32 + l] += g * vep[32 + l];
    }
}

// ---------------------------------------------------------------------------
// Flash attention, TF32 tensor cores — EXACT verified R11 kernel (LDG
// double-buffer, BM=128, 2 CTA/SM), except the final store writes fp16 g_y_h.
// ---------------------------------------------------------------------------
#define PADQ 68
#define PADK 68
#define PADV 72
#define OK0 (128 * PADQ)
#define OV0 (OK0 + 64 * PADK)
#define OK1 (OV0 + 64 * PADV)
#define OV1 (OK1 + 64 * PADK)
#define SM_FLOATS (OV1 + 64 * PADV)

__device__ __forceinline__
void load_kv_tile(const float* __restrict__ kptr, const float* __restrict__ vptr,
                  int k0, int tid, float* __restrict__ kd_base,
                  float* __restrict__ vd_base)
{
    const int r  = tid >> 2;
    const int c0 = (tid & 3) << 4;
    const float* ks = kptr + (size_t)(k0 + r) * QKROW + c0;
    const float* vs = vptr + (size_t)(k0 + r) * QKROW + c0;
    float* kd = kd_base + r * PADK + c0;
    float* vd = vd_base + r * PADV + c0;
    #pragma unroll
    for (int i = 0; i < 16; i += 4) {
        float4 k4 = *(const float4*)(ks + i);
        float4 v4 = *(const float4*)(vs + i);
        kd[i+0] = tf32r(k4.x); kd[i+1] = tf32r(k4.y);
        kd[i+2] = tf32r(k4.z); kd[i+3] = tf32r(k4.w);
        vd[i+0] = tf32r(v4.x); vd[i+1] = tf32r(v4.y);
        vd[i+2] = tf32r(v4.z); vd[i+3] = tf32r(v4.w);
    }
}

__global__ __launch_bounds__(256, 2)
void attn(const int* __restrict__ wlp)
{
    extern __shared__ float sm[];
    float* QP = sm;                 // Q tile, then P (exp scores)

    const int tid  = threadIdx.x;
    const int w    = tid >> 5;
    const int lane = tid & 31;
    const int g    = lane >> 2;
    const int qid  = lane & 3;
    const int qt = blockIdx.x;      // 0..15
    const int h  = blockIdx.y;      // 0..15
    const int b  = blockIdx.z;      // 0..1
    const int window = *wlp;
    const int kv = h >> 2;
    const int q0 = qt << 7;

    const float* rowbase = g_qkv + (size_t)b * TSEQ * QKROW;
    const float* qptr = rowbase + h * 64;
    const float* kptr = rowbase + 1024 + kv * 64;
    const float* vptr = rowbase + 1280 + kv * 64;

    {   // load Q tile (warp w loads exactly its own rows 16w..16w+15)
        const int r = tid >> 1;
        const int c0 = (tid & 1) << 5;
        const float* src = qptr + (size_t)(q0 + r) * QKROW + c0;
        float* dst = QP + r * PADQ + c0;
        #pragma unroll
        for (int i = 0; i < 32; i += 4) {
            float4 v4 = *(const float4*)(src + i);
            dst[i+0] = tf32r(v4.x); dst[i+1] = tf32r(v4.y);
            dst[i+2] = tf32r(v4.z); dst[i+3] = tf32r(v4.w);
        }
    }
    __syncwarp();

    const int mrow = (w << 4) + g;
    const int qlo = q0 + mrow;
    const int qhi = qlo + 8;

    uint32_t qf[8][4];
    #pragma unroll
    for (int k8 = 0; k8 < 8; k8++) {
        qf[k8][0] = __float_as_uint(QP[(mrow    ) * PADQ + (k8 << 3) + qid]);
        qf[k8][1] = __float_as_uint(QP[(mrow + 8) * PADQ + (k8 << 3) + qid]);
        qf[k8][2] = __float_as_uint(QP[(mrow    ) * PADQ + (k8 << 3) + qid + 4]);
        qf[k8][3] = __float_as_uint(QP[(mrow + 8) * PADQ + (k8 << 3) + qid + 4]);
    }
    __syncwarp();

    float o[8][4];
    #pragma unroll
    for (int nt = 0; nt < 8; nt++)
        #pragma unroll
        for (int r = 0; r < 4; r++) o[nt][r] = 0.f;
    float m_lo = -1e30f, m_hi = -1e30f, l_lo = 0.f, l_hi = 0.f;

    int lo = q0 - window; if (lo < 0) lo = 0;
    const int kt0 = lo >> 6;
    const int ktmax = (q0 + 127) >> 6;

    load_kv_tile(kptr, vptr, kt0 << 6, tid, sm + OK0, sm + OV0);
    __syncthreads();
    int p = 0;

    for (int kt = kt0; kt <= ktmax; kt++) {
        const int k0 = kt << 6;
        const float* Kc = sm + (p ? OK1 : OK0);
        const float* Vc = sm + (p ? OV1 : OV0);

        float s[8][4];
        #pragma unroll
        for (int nt = 0; nt < 8; nt++)
            #pragma unroll
            for (int r = 0; r < 4; r++) s[nt][r] = 0.f;
        #pragma unroll
        for (int k8 = 0; k8 < 8; k8++) {
            const int kk = k8 << 3;
            #pragma unroll
            for (int nt = 0; nt < 8; nt++) {
                uint32_t bfr[2];
                bfr[0] = __float_as_uint(Kc[((nt << 3) + g) * PADK + kk + qid]);
                bfr[1] = __float_as_uint(Kc[((nt << 3) + g) * PADK + kk + qid + 4]);
                mma_tf32(s[nt], qf[k8], bfr);
            }
        }

        const bool interior = (k0 + 63 <= q0) && (q0 + 127 - k0 <= window);
        float rx_lo = -1e30f, rx_hi = -1e30f;
        if (interior) {
            #pragma unroll
            for (int nt = 0; nt < 8; nt++) {
                #pragma unroll
                for (int c = 0; c < 2; c++) {
                    s[nt][c]     *= 0.125f;
                    s[nt][2 + c] *= 0.125f;
                    rx_lo = fmaxf(rx_lo, s[nt][c]);
                    rx_hi = fmaxf(rx_hi, s[nt][2 + c]);
                }
            }
        } else {
            #pragma unroll
            for (int nt = 0; nt < 8; nt++) {
                #pragma unroll
                for (int c = 0; c < 2; c++) {
                    const int kj = k0 + (nt << 3) + (qid << 1) + c;
                    const bool ok_lo = (kj <= qlo) && (qlo - kj <= window);
                    const bool ok_hi = (kj <= qhi) && (qhi - kj <= window);
                    s[nt][c]     = ok_lo ? s[nt][c]     * 0.125f : -1e30f;
                    s[nt][2 + c] = ok_hi ? s[nt][2 + c] * 0.125f : -1e30f;
                    rx_lo = fmaxf(rx_lo, s[nt][c]);
                    rx_hi = fmaxf(rx_hi, s[nt][2 + c]);
                }
            }
        }
        rx_lo = fmaxf(rx_lo, __shfl_xor_sync(0xffffffffu, rx_lo, 1));
        rx_lo = fmaxf(rx_lo, __shfl_xor_sync(0xffffffffu, rx_lo, 2));
        rx_hi = fmaxf(rx_hi, __shfl_xor_sync(0xffffffffu, rx_hi, 1));
        rx_hi = fmaxf(rx_hi, __shfl_xor_sync(0xffffffffu, rx_hi, 2));

        const float mn_lo = fmaxf(m_lo, rx_lo);
        const float mn_hi = fmaxf(m_hi, rx_hi);
        const float cr_lo = __expf(m_lo - mn_lo);
        const float cr_hi = __expf(m_hi - mn_hi);
        float rs_lo = 0.f, rs_hi = 0.f;
        #pragma unroll
        for (int nt = 0; nt < 8; nt++) {
            float e0 = __expf(s[nt][0] - mn_lo);
            float e1 = __expf(s[nt][1] - mn_lo);
            float e2 = __expf(s[nt][2] - mn_hi);
            float e3 = __expf(s[nt][3] - mn_hi);
            rs_lo += e0 + e1;
            rs_hi += e2 + e3;
            const int pc = (nt << 3) + (qid << 1);
            *(float2*)&QP[(mrow    ) * PADQ + pc] = make_float2(tf32r(e0), tf32r(e1));
            *(float2*)&QP[(mrow + 8) * PADQ + pc] = make_float2(tf32r(e2), tf32r(e3));
        }
        rs_lo += __shfl_xor_sync(0xffffffffu, rs_lo, 1);
        rs_lo += __shfl_xor_sync(0xffffffffu, rs_lo, 2);
        rs_hi += __shfl_xor_sync(0xffffffffu, rs_hi, 1);
        rs_hi += __shfl_xor_sync(0xffffffffu, rs_hi, 2);
        m_lo = mn_lo; m_hi = mn_hi;
        l_lo = l_lo * cr_lo + rs_lo;
        l_hi = l_hi * cr_hi + rs_hi;
        #pragma unroll
        for (int nt = 0; nt < 8; nt++) {
            o[nt][0] *= cr_lo; o[nt][1] *= cr_lo;
            o[nt][2] *= cr_hi; o[nt][3] *= cr_hi;
        }
        __syncwarp();

        #pragma unroll
        for (int k8 = 0; k8 < 8; k8++) {
            const int kk = k8 << 3;
            uint32_t a[4];
            a[0] = __float_as_uint(QP[(mrow    ) * PADQ + kk + qid]);
            a[1] = __float_as_uint(QP[(mrow + 8) * PADQ + kk + qid]);
            a[2] = __float_as_uint(QP[(mrow    ) * PADQ + kk + qid + 4]);
            a[3] = __float_as_uint(QP[(mrow + 8) * PADQ + kk + qid + 4]);
            #pragma unroll
            for (int nt = 0; nt < 8; nt++) {
                uint32_t bfr[2];
                bfr[0] = __float_as_uint(Vc[(kk + qid    ) * PADV + (nt << 3) + g]);
                bfr[1] = __float_as_uint(Vc[(kk + qid + 4) * PADV + (nt << 3) + g]);
                mma_tf32(o[nt], a, bfr);
            }
        }
        __syncwarp();

        if (kt < ktmax)
            load_kv_tile(kptr, vptr, (kt + 1) << 6, tid,
                         sm + (p ? OK0 : OK1), sm + (p ? OV0 : OV1));
        __syncthreads();
        p ^= 1;
    }

    const float inv_lo = 1.0f / l_lo;
    const float inv_hi = 1.0f / l_hi;
    __half* ylo = g_y_h + (size_t)(b * TSEQ + qlo) * 1024 + h * 64;
    __half* yhi = g_y_h + (size_t)(b * TSEQ + qhi) * 1024 + h * 64;
    #pragma unroll
    for (int nt = 0; nt < 8; nt++) {
        const int c = (nt << 3) + (qid << 1);
        *(__half2*)(ylo + c) = __floats2half2_rn(o[nt][0] * inv_lo, o[nt][1] * inv_lo);
        *(__half2*)(yhi + c) = __floats2half2_rn(o[nt][2] * inv_hi, o[nt][3] * inv_hi);
    }
}

// ---------------------------------------------------------------------------
extern "C" void kernel_launch(void* const* d_in, const int* in_sizes, int n_in,
                              void* d_out, int out_size)
{
    const float* x  = (const float*)d_in[0];
    const float* ve = (const float*)d_in[1];
    const float* cs = (const float*)d_in[2];
    const float* sn = (const float*)d_in[3];
    const float* Wq = (const float*)d_in[4];
    const float* Wk = (const float*)d_in[5];
    const float* Wv = (const float*)d_in[6];
    const float* Wo = (const float*)d_in[7];
    const float* Wg = (const float*)d_in[8];
    const int*   wl = (const int*)d_in[9];
    float* out = (float*)d_out;

    // Idempotent host-side calls; safe under graph capture, no static guards.
    cudaFuncSetAttribute(attn, cudaFuncAttributeMaxDynamicSharedMemorySize,
                         SM_FLOATS * sizeof(float));
    cudaFuncSetAttribute(gemm_qkv, cudaFuncAttributeMaxDynamicSharedMemorySize,
                         HSM_BYTES);
    cudaFuncSetAttribute(gemm_out, cudaFuncAttributeMaxDynamicSharedMemorySize,
                         HSM_BYTES);

    // fp16 conversions of x and all weight matrices
    to_half<<<(SO + 255) / 256, 256>>>(x, Wq, Wk, Wv, Wo);

    // Fused QKV projection (fp16 inputs, fp32 out) -> g_qkv
    gemm_qkv<<<dim3(6, 32), 256, HSM_BYTES>>>(0);

    // gate*ve add, rotary + rmsnorm * QK_SCALE
    postproc<<<MTOT, 768>>>(x, ve, cs, sn, Wg);

    // sliding-window flash attention (TF32 tensor cores) -> g_y_h (fp16)
    attn<<<dim3(16, NHEAD, 2), 256, SM_FLOATS * sizeof(float)>>>(wl);

    // output projection: out = g_y @ Wo^T (fp16 inputs, fp32 out)
    gemm_out<<<dim3(4, 32), 256, HSM_BYTES>>>(out);
}